// round 1
// baseline (speedup 1.0000x reference)
#include <cuda_runtime.h>
#include <cstdint>

#define Bb   32
#define Tt   2048
#define Hh   256
#define G3   768
#define NVv  18
#define NOo  17
#define CL   4       // CTAs per cluster (one cluster per batch)
#define NT   384     // threads per scan CTA
#define NCTA (Bb * CL)

// Scratch (allocation-free rule: __device__ globals)
__device__ float g_G[NVv * G3];          // gi lookup table: (embed @ W_ih + b_ih)
__device__ float g_hout[Bb * Tt * Hh];   // h states for the head GEMM (64 MB)

// ---------------- helpers ----------------
__device__ __forceinline__ unsigned smem_u32(const void* p) {
    return (unsigned)__cvta_generic_to_shared(p);
}
__device__ __forceinline__ unsigned mapa_u32(unsigned local, int rank) {
    unsigned r;
    asm("mapa.shared::cluster.u32 %0, %1, %2;" : "=r"(r) : "r"(local), "r"(rank));
    return r;
}
__device__ __forceinline__ unsigned long long pack2(float lo, float hi) {
    unsigned long long v;
    asm("mov.b64 %0, {%1, %2};" : "=l"(v) : "f"(lo), "f"(hi));
    return v;
}
__device__ __forceinline__ float2 unpack2(unsigned long long v) {
    float lo, hi;
    asm("mov.b64 {%0, %1}, %2;" : "=f"(lo), "=f"(hi) : "l"(v));
    return make_float2(lo, hi);
}
// packed 2-wide fp32 FMA (SASS FFMA2) — doubles f32 MAC rate vs FFMA
__device__ __forceinline__ unsigned long long fma2(unsigned long long a,
                                                   unsigned long long b,
                                                   unsigned long long c) {
    unsigned long long d;
    asm("fma.rn.f32x2 %0, %1, %2, %3;" : "=l"(d) : "l"(a), "l"(b), "l"(c));
    return d;
}
__device__ __forceinline__ float fast_sigmoid(float x) {
    float e;
    asm("ex2.approx.f32 %0, %1;" : "=f"(e) : "f"(-1.4426950408889634f * x));
    float r;
    asm("rcp.approx.f32 %0, %1;" : "=f"(r) : "f"(1.0f + e));
    return r;
}
__device__ __forceinline__ float fast_tanh(float x) {
    return fmaf(2.0f, fast_sigmoid(2.0f * x), -1.0f);
}

// ---------------- kernel 1: gi lookup table ----------------
// G[v][c] = sum_k embed[v][k] * W_ih[k][c] + b_ih[c]
__global__ __launch_bounds__(256) void gtable_kernel(const float* __restrict__ embed,
                                                     const float* __restrict__ W_ih,
                                                     const float* __restrict__ b_ih) {
    __shared__ float e_s[Hh];
    const int v = blockIdx.x;
    if (threadIdx.x < Hh) e_s[threadIdx.x] = embed[v * Hh + threadIdx.x];
    __syncthreads();
    for (int c = threadIdx.x; c < G3; c += blockDim.x) {
        float acc = b_ih[c];
        #pragma unroll 8
        for (int k = 0; k < Hh; k++) acc = fmaf(e_s[k], W_ih[k * G3 + c], acc);
        g_G[v * G3 + c] = acc;
    }
}

// ---------------- kernel 2: GRU scan ----------------
// One cluster of 4 CTAs per batch element. CTA `rank` owns:
//   - k-slice of h: rows [64*rank, 64*rank+64)  (weights for ALL 768 gate cols, in registers)
//   - gate columns {g*256 + 64*rank + j : g in 0..2, j in 0..63} for the epilogue
// Per step: local-h FMA -> DSMEM partial push -> cluster barrier -> gates -> local h update.
__global__ __launch_bounds__(NT, 1) __cluster_dims__(CL, 1, 1)
void scan_kernel(const int* __restrict__ tokens,
                 const float* __restrict__ W_hh,
                 const float* __restrict__ b_hh,
                 float* __restrict__ betas) {
    __shared__ float G_s[NVv * 192];                              // gi table, my 192 cols
    __shared__ int   tok_s[Tt];
    __shared__ __align__(16) float part[2][CL * 192];             // ping-pong partial sums
    __shared__ __align__(16) unsigned long long h_s64[32];        // my 64 h values (f32 pairs)
    __shared__ float bhh_s[192];

    const int t0    = threadIdx.x;
    const int rank  = blockIdx.x & (CL - 1);
    const int batch = blockIdx.x >> 2;
    const int c0    = 2 * t0;                                     // this thread's 2 gate cols

    // ---- prologue: weights into registers (64 k-rows x 2 cols, packed as f32x2 along k)
    unsigned long long w0[32], w1[32];
    {
        const float* Wb = W_hh + (size_t)(64 * rank) * G3;
        #pragma unroll
        for (int kk = 0; kk < 32; kk++) {
            float a0 = Wb[(2 * kk) * G3 + c0];
            float b0 = Wb[(2 * kk + 1) * G3 + c0];
            float a1 = Wb[(2 * kk) * G3 + c0 + 1];
            float b1 = Wb[(2 * kk + 1) * G3 + c0 + 1];
            w0[kk] = pack2(a0, b0);
            w1[kk] = pack2(a1, b1);
        }
    }
    for (int i = t0; i < NVv * 192; i += NT) {
        int v = i / 192, s = i - v * 192;
        int g = s >> 6, j = s & 63;
        G_s[i] = g_G[v * G3 + (g << 8) + (rank << 6) + j];
    }
    for (int i = t0; i < 192; i += NT) {
        int g = i >> 6, j = i & 63;
        bhh_s[i] = b_hh[(g << 8) + (rank << 6) + j];
    }
    for (int i = t0; i < Tt; i += NT) tok_s[i] = tokens[batch * Tt + i];
    if (t0 < 32) h_s64[t0] = 0ULL;   // h0 = 0

    // ---- destination DSMEM addresses for this thread's partial pair
    // col C = 256*g + 64*peer + slot  -> peer CTA, slot within gate g
    const int g    = c0 >> 8;
    const int idx  = c0 & 255;
    const int peer = idx >> 6;
    const int slot = idx & 63;       // even; pair covers slot, slot+1
    const unsigned dst0 = mapa_u32(smem_u32(&part[0][rank * 192 + g * 64 + slot]), peer);
    const unsigned dst1 = mapa_u32(smem_u32(&part[1][rank * 192 + g * 64 + slot]), peer);

    __syncthreads();

    float* out_beta = betas  + (size_t)(batch * Tt) * Hh + (rank << 6);
    float* out_h    = g_hout + (size_t)(batch * Tt) * Hh + (rank << 6);

    for (int t = 0; t < Tt; t++) {
        // ---- partial gate sums over local h slice (registers x smem-broadcast)
        unsigned long long acc0 = 0ULL, acc1 = 0ULL;
        #pragma unroll
        for (int kk = 0; kk < 32; kk++) {
            unsigned long long h2 = h_s64[kk];
            acc0 = fma2(w0[kk], h2, acc0);
            acc1 = fma2(w1[kk], h2, acc1);
        }
        float2 a0 = unpack2(acc0), a1 = unpack2(acc1);
        unsigned long long pv = pack2(a0.x + a0.y, a1.x + a1.y);
        unsigned d = (t & 1) ? dst1 : dst0;
        asm volatile("st.shared::cluster.b64 [%0], %1;" :: "r"(d), "l"(pv) : "memory");

        // ---- cluster barrier (release/acquire orders the DSMEM stores)
        asm volatile("barrier.cluster.arrive.aligned;" ::: "memory");
        asm volatile("barrier.cluster.wait.aligned;"   ::: "memory");

        // ---- gate epilogue: 64 threads, one h-output each
        if (t0 < 64) {
            const float* pb = part[t & 1];
            float gr = pb[t0]       + pb[192 + t0]       + pb[384 + t0]       + pb[576 + t0]       + bhh_s[t0];
            float gz = pb[64 + t0]  + pb[192 + 64 + t0]  + pb[384 + 64 + t0]  + pb[576 + 64 + t0]  + bhh_s[64 + t0];
            float gn = pb[128 + t0] + pb[192 + 128 + t0] + pb[384 + 128 + t0] + pb[576 + 128 + t0] + bhh_s[128 + t0];
            const int tok = tok_s[t];
            const float* Gr = &G_s[tok * 192];
            float r  = fast_sigmoid(Gr[t0] + gr);
            float z  = fast_sigmoid(Gr[64 + t0] + gz);
            float n  = fast_tanh(Gr[128 + t0] + fmaf(r, gn, 0.0f));
            float ho = ((const float*)h_s64)[t0];
            float hn = fmaf(z, ho - n, n);              // (1-z)*n + z*h
            ((float*)h_s64)[t0] = hn;
            out_beta[(size_t)t * Hh + t0] = z;
            out_h[(size_t)t * Hh + t0]    = hn;
        }
        __syncthreads();   // h_s64 update visible before next FMA pass
    }
}

// ---------------- kernel 3: head GEMM ----------------
// logits[row][o] = h[row] . W_head[:,o] + b_head[o];  row = b*T+t
__global__ __launch_bounds__(256) void head_kernel(const float* __restrict__ W_head,
                                                   const float* __restrict__ b_head,
                                                   float* __restrict__ logits) {
    __shared__ float w_s[NOo * Hh];   // transposed: w_s[o*H + k]
    __shared__ float b_s[NOo];
    for (int i = threadIdx.x; i < NOo * Hh; i += blockDim.x) {
        int o = i / Hh, k = i - o * Hh;
        w_s[i] = W_head[k * NOo + o];
    }
    if (threadIdx.x < NOo) b_s[threadIdx.x] = b_head[threadIdx.x];
    __syncthreads();

    const int row = blockIdx.x * blockDim.x + threadIdx.x;
    const float4* hr = (const float4*)(g_hout + (size_t)row * Hh);
    float acc[NOo];
    #pragma unroll
    for (int o = 0; o < NOo; o++) acc[o] = b_s[o];
    for (int k4 = 0; k4 < Hh / 4; k4++) {
        float4 hv = hr[k4];
        #pragma unroll
        for (int o = 0; o < NOo; o++) {
            const float4 wv = *(const float4*)&w_s[o * Hh + 4 * k4];
            acc[o] = fmaf(hv.x, wv.x, fmaf(hv.y, wv.y, fmaf(hv.z, wv.z, fmaf(hv.w, wv.w, acc[o]))));
        }
    }
    float* out = logits + (size_t)row * NOo;
    #pragma unroll
    for (int o = 0; o < NOo; o++) out[o] = acc[o];
}

// ---------------- launch ----------------
extern "C" void kernel_launch(void* const* d_in, const int* in_sizes, int n_in,
                              void* d_out, int out_size) {
    const int*   tokens = (const int*)d_in[0];
    const float* embed  = (const float*)d_in[1];
    const float* W_ih   = (const float*)d_in[2];
    const float* W_hh   = (const float*)d_in[3];
    const float* b_ih   = (const float*)d_in[4];
    const float* b_hh   = (const float*)d_in[5];
    const float* W_head = (const float*)d_in[6];
    const float* b_head = (const float*)d_in[7];
    (void)in_sizes; (void)n_in; (void)out_size;

    float* out    = (float*)d_out;
    float* logits = out;                        // [B*T, 17]
    float* betas  = out + (size_t)Bb * Tt * NOo; // [B*T, 256]

    gtable_kernel<<<NVv, 256>>>(embed, W_ih, b_ih);
    scan_kernel<<<NCTA, NT>>>(tokens, W_hh, b_hh, betas);
    head_kernel<<<(Bb * Tt) / 256, 256>>>(W_head, b_head, logits);
}

// round 2
// speedup vs baseline: 1.4425x; 1.4425x over previous
#include <cuda_runtime.h>
#include <cstdint>

#define Bb   32
#define Tt   2048
#define Hh   256
#define G3   768
#define NVv  18
#define NOo  17
#define CL   4       // CTAs per cluster (one cluster per batch)
#define NT   384     // threads per scan CTA
#define NCTA (Bb * CL)

// Scratch (allocation-free rule: __device__ globals)
__device__ float g_hout[Bb * Tt * Hh];   // h states for the head GEMM (64 MB)

// ---------------- helpers ----------------
__device__ __forceinline__ unsigned smem_u32(const void* p) {
    return (unsigned)__cvta_generic_to_shared(p);
}
__device__ __forceinline__ unsigned mapa_u32(unsigned local, int rank) {
    unsigned r;
    asm("mapa.shared::cluster.u32 %0, %1, %2;" : "=r"(r) : "r"(local), "r"(rank));
    return r;
}
__device__ __forceinline__ unsigned long long pack2(float lo, float hi) {
    unsigned long long v;
    asm("mov.b64 %0, {%1, %2};" : "=l"(v) : "f"(lo), "f"(hi));
    return v;
}
__device__ __forceinline__ float2 unpack2(unsigned long long v) {
    float lo, hi;
    asm("mov.b64 {%0, %1}, %2;" : "=f"(lo), "=f"(hi) : "l"(v));
    return make_float2(lo, hi);
}
// packed 2-wide fp32 FMA (SASS FFMA2)
__device__ __forceinline__ unsigned long long fma2(unsigned long long a,
                                                   unsigned long long b,
                                                   unsigned long long c) {
    unsigned long long d;
    asm("fma.rn.f32x2 %0, %1, %2, %3;" : "=l"(d) : "l"(a), "l"(b), "l"(c));
    return d;
}
__device__ __forceinline__ float fast_sigmoid(float x) {
    float e;
    asm("ex2.approx.f32 %0, %1;" : "=f"(e) : "f"(-1.4426950408889634f * x));
    float r;
    asm("rcp.approx.f32 %0, %1;" : "=f"(r) : "f"(1.0f + e));
    return r;
}
__device__ __forceinline__ float fast_tanh(float x) {
    return fmaf(2.0f, fast_sigmoid(2.0f * x), -1.0f);
}

// ---------------- kernel 1: GRU scan ----------------
// One cluster of 4 CTAs per batch. CTA `rank` owns 192 gate columns:
//   { g*256 + rank*64 + j : g in {0,1,2}, j in [0,64) }
// over the FULL K=256 h dimension (weights in registers: 384 thr x 128 f32).
// Thread t: col-pair cp = t%96 (2 cols), k-quarter kq = t/96 (64 k-values).
// Per step: FMA (full gate sums, local) -> bar -> 64-thread gate epilogue
// produces this CTA's 64 new h values -> st.async h to all 4 cluster CTAs
// with mbarrier complete_tx -> all threads try_wait (acquire.cluster).
// No cluster barrier on the critical path.
__global__ __launch_bounds__(NT, 1) __cluster_dims__(CL, 1, 1)
void scan_kernel(const int* __restrict__ tokens,
                 const float* __restrict__ embed,
                 const float* __restrict__ W_ih,
                 const float* __restrict__ b_ih,
                 const float* __restrict__ W_hh,
                 const float* __restrict__ b_hh,
                 float* __restrict__ betas) {
    __shared__ float G_s[NVv * 192];                 // gi table, my 192 cols
    __shared__ float embed_s[NVv * Hh];
    __shared__ int   tok_s[Tt];
    __shared__ __align__(16) float part[4 * 192];    // k-quarter partial sums
    __shared__ __align__(16) unsigned long long hbuf[2][Hh / 2];  // full h, ping-pong
    __shared__ float bhh_s[192];
    __shared__ __align__(8) unsigned long long mbar[2];

    const int t0    = threadIdx.x;
    const int rank  = blockIdx.x & (CL - 1);
    const int batch = blockIdx.x >> 2;
    const int cp    = t0 % 96;          // col pair index
    const int kq    = t0 / 96;          // k quarter (warp-uniform: 96 = 3 warps)
    const int c0    = 2 * cp;           // local col in [0,192)
    const int C0    = ((c0 >> 6) << 8) + (rank << 6) + (c0 & 63);  // global col
    const int C1    = C0 + 1;

    // ---- prologue smem loads
    for (int i = t0; i < NVv * Hh; i += NT) embed_s[i] = embed[i];
    for (int i = t0; i < 192; i += NT) {
        int g = i >> 6, j = i & 63;
        bhh_s[i] = b_hh[(g << 8) + (rank << 6) + j];
    }
    for (int i = t0; i < Tt; i += NT) tok_s[i] = tokens[batch * Tt + i];
    if (t0 < Hh / 2) hbuf[0][t0] = 0ULL;             // h0 = 0
    if (t0 == 0) {
        asm volatile("mbarrier.init.shared.b64 [%0], 1;" :: "r"(smem_u32(&mbar[0])) : "memory");
        asm volatile("mbarrier.init.shared.b64 [%0], 1;" :: "r"(smem_u32(&mbar[1])) : "memory");
    }
    __syncthreads();

    // ---- G table for my 192 cols: G[v][c] = embed[v] . W_ih[:,C] + b_ih[C]
    {
        float acc[9]; int Cg[9]; int vv[9];
        #pragma unroll
        for (int i = 0; i < 9; i++) {
            int e = t0 + i * NT;
            int v = e / 192, c = e - v * 192;
            int C = ((c >> 6) << 8) + (rank << 6) + (c & 63);
            acc[i] = b_ih[C]; Cg[i] = C; vv[i] = v * Hh;
        }
        for (int k = 0; k < Hh; k++) {
            const float* Wk = W_ih + (size_t)k * G3;
            #pragma unroll
            for (int i = 0; i < 9; i++)
                acc[i] = fmaf(embed_s[vv[i] + k], Wk[Cg[i]], acc[i]);
        }
        #pragma unroll
        for (int i = 0; i < 9; i++) {
            int e = t0 + i * NT;
            int v = e / 192, c = e - v * 192;
            G_s[v * 192 + c] = acc[i];
        }
    }

    // ---- weights into registers: 2 cols x 64 k (32 f32x2 pairs each)
    unsigned long long w0[32], w1[32];
    {
        const float* Wb = W_hh + (size_t)(kq * 64) * G3;
        #pragma unroll
        for (int kk = 0; kk < 32; kk++) {
            w0[kk] = pack2(Wb[(2 * kk) * G3 + C0], Wb[(2 * kk + 1) * G3 + C0]);
            w1[kk] = pack2(Wb[(2 * kk) * G3 + C1], Wb[(2 * kk + 1) * G3 + C1]);
        }
    }
    __syncthreads();
    // cluster-wide: mbarrier inits visible before any st.async
    asm volatile("barrier.cluster.arrive.aligned;" ::: "memory");
    asm volatile("barrier.cluster.wait.aligned;"   ::: "memory");

    float* out_beta = betas  + (size_t)(batch * Tt) * Hh + (rank << 6);
    float* out_h    = g_hout + (size_t)(batch * Tt) * Hh + (rank << 6);

    const unsigned mb_u32  = smem_u32(&mbar[0]);
    const unsigned hb0_u32 = smem_u32(&hbuf[0][0]);
    const unsigned hb1_u32 = smem_u32(&hbuf[1][0]);

    for (int t = 0; t < Tt; t++) {
        const int p = t & 1;
        if (t0 == 0) {
            // 4 CTAs x 64 threads x 4B = 1024 expected tx bytes this phase
            asm volatile("mbarrier.arrive.expect_tx.shared.b64 _, [%0], %1;"
                         :: "r"(mb_u32 + p * 8), "r"(1024) : "memory");
        }

        // ---- full gate sums over my k-quarter (regs x smem-broadcast)
        unsigned long long acc0 = 0ULL, acc1 = 0ULL;
        const unsigned long long* hb = &hbuf[p][kq << 5];
        #pragma unroll
        for (int kk = 0; kk < 32; kk++) {
            unsigned long long h2 = hb[kk];
            acc0 = fma2(w0[kk], h2, acc0);
            acc1 = fma2(w1[kk], h2, acc1);
        }
        float2 a0 = unpack2(acc0), a1 = unpack2(acc1);
        *(float2*)&part[kq * 192 + c0] = make_float2(a0.x + a0.y, a1.x + a1.y);
        __syncthreads();

        // ---- gate epilogue: 64 threads, one h-output each
        if (t0 < 64) {
            const int j = t0;
            float sr = part[j]       + part[192 + j]       + part[384 + j]       + part[576 + j]       + bhh_s[j];
            float sz = part[64 + j]  + part[192 + 64 + j]  + part[384 + 64 + j]  + part[576 + 64 + j]  + bhh_s[64 + j];
            float sn = part[128 + j] + part[192 + 128 + j] + part[384 + 128 + j] + part[576 + 128 + j] + bhh_s[128 + j];
            const int tok = tok_s[t];
            const float* Gr = &G_s[tok * 192];
            float r  = fast_sigmoid(Gr[j] + sr);
            float z  = fast_sigmoid(Gr[64 + j] + sz);
            float n  = fast_tanh(fmaf(r, sn, Gr[128 + j]));
            const int gidx = (rank << 6) + j;
            float ho = ((const float*)&hbuf[p][0])[gidx];
            float hn = fmaf(z, ho - n, n);              // (1-z)*n + z*h

            const unsigned loc  = ((p ^ 1) ? hb1_u32 : hb0_u32) + 4u * gidx;
            const unsigned mloc = mb_u32 + p * 8;
            #pragma unroll
            for (int r2 = 0; r2 < CL; r2++) {
                unsigned d = mapa_u32(loc, r2);
                unsigned m = mapa_u32(mloc, r2);
                asm volatile(
                    "st.async.shared::cluster.mbarrier::complete_tx::bytes.b32 [%0], %1, [%2];"
                    :: "r"(d), "f"(hn), "r"(m) : "memory");
            }
            out_beta[(size_t)t * Hh + j] = z;
            out_h[(size_t)t * Hh + j]    = hn;
        }

        // ---- wait: all 4 CTAs' h stores delivered (acquire at cluster scope)
        {
            const unsigned m   = mb_u32 + p * 8;
            const unsigned par = (t >> 1) & 1;
            unsigned done;
            do {
                asm volatile(
                    "{\n\t.reg .pred P;\n\t"
                    "mbarrier.try_wait.parity.acquire.cluster.shared::cta.b64 P, [%1], %2, 0x989680;\n\t"
                    "selp.b32 %0, 1, 0, P;\n\t}"
                    : "=r"(done) : "r"(m), "r"(par) : "memory");
            } while (!done);
        }
    }
}

// ---------------- kernel 2: head GEMM ----------------
__global__ __launch_bounds__(256) void head_kernel(const float* __restrict__ W_head,
                                                   const float* __restrict__ b_head,
                                                   float* __restrict__ logits) {
    __shared__ float w_s[NOo * Hh];   // transposed: w_s[o*H + k]
    __shared__ float b_s[NOo];
    for (int i = threadIdx.x; i < NOo * Hh; i += blockDim.x) {
        int o = i / Hh, k = i - o * Hh;
        w_s[i] = W_head[k * NOo + o];
    }
    if (threadIdx.x < NOo) b_s[threadIdx.x] = b_head[threadIdx.x];
    __syncthreads();

    const int row = blockIdx.x * blockDim.x + threadIdx.x;
    const float4* hr = (const float4*)(g_hout + (size_t)row * Hh);
    float acc[NOo];
    #pragma unroll
    for (int o = 0; o < NOo; o++) acc[o] = b_s[o];
    for (int k4 = 0; k4 < Hh / 4; k4++) {
        float4 hv = hr[k4];
        #pragma unroll
        for (int o = 0; o < NOo; o++) {
            const float4 wv = *(const float4*)&w_s[o * Hh + 4 * k4];
            acc[o] = fmaf(hv.x, wv.x, fmaf(hv.y, wv.y, fmaf(hv.z, wv.z, fmaf(hv.w, wv.w, acc[o]))));
        }
    }
    float* out = logits + (size_t)row * NOo;
    #pragma unroll
    for (int o = 0; o < NOo; o++) out[o] = acc[o];
}

// ---------------- launch ----------------
extern "C" void kernel_launch(void* const* d_in, const int* in_sizes, int n_in,
                              void* d_out, int out_size) {
    const int*   tokens = (const int*)d_in[0];
    const float* embed  = (const float*)d_in[1];
    const float* W_ih   = (const float*)d_in[2];
    const float* W_hh   = (const float*)d_in[3];
    const float* b_ih   = (const float*)d_in[4];
    const float* b_hh   = (const float*)d_in[5];
    const float* W_head = (const float*)d_in[6];
    const float* b_head = (const float*)d_in[7];
    (void)in_sizes; (void)n_in; (void)out_size;

    float* out    = (float*)d_out;
    float* logits = out;                          // [B*T, 17]
    float* betas  = out + (size_t)Bb * Tt * NOo;  // [B*T, 256]

    scan_kernel<<<NCTA, NT>>>(tokens, embed, W_ih, b_ih, W_hh, b_hh, betas);
    head_kernel<<<(Bb * Tt) / 256, 256>>>(W_head, b_head, logits);
}